// round 4
// baseline (speedup 1.0000x reference)
#include <cuda_runtime.h>
#include <cstdint>

// T=4 tables, E=1,000,000 rows/table, D=128 dims, B=8192 bags, L=32 bag length
// indices: [T, B, L] (int32 OR int64 — detected at runtime)
// weights: fp32 [T, E, D]; output: fp32 [B, T*D]
// out[b, t*D + d] = sum_l weights[t, indices[t,b,l], d]

#define T_TABLES 4
#define E_ROWS   1000000
#define D_DIM    128
#define B_BATCH  8192
#define L_BAG    32

// 1 = indices are int64, 0 = int32. Set by probe kernel each launch (deterministic).
__device__ int g_idx_is64;

// One parallel memory round-trip. If the buffer is really int32, each int64
// view's hi-word is a random row id in [0,1M); it passes the range check only
// if that hi-word is exactly 0 (P=1e-6 per value, ~0 for all 32).
__global__ void probe_idx_dtype(const long long* __restrict__ idx)
{
    const int lane = threadIdx.x;
    const long long v = idx[lane];
    const unsigned bad = __ballot_sync(0xffffffffu, v < 0 || v >= E_ROWS);
    if (lane == 0) g_idx_is64 = (bad == 0u) ? 1 : 0;
}

// One warp per bag b, looping over the 4 tables. 8192 warps = single wave.
// Per table: each lane holds one bag index; a warp-wide bitonic sort orders
// the 32 indices ascending so the 32 x 512B row gathers issue in address
// order (better DRAM page locality). Sum pooling is order-invariant.
__global__ __launch_bounds__(256) void embbag_kernel(
    const void*  __restrict__ indices_raw,   // [T*B*L] int32 or int64
    const float* __restrict__ weights,       // [T*E*D]
    float*       __restrict__ out)           // [B*T*D]
{
    const int lane = threadIdx.x & 31;
    const int b    = blockIdx.x * 8 + (threadIdx.x >> 5);   // 0..8191, exact

    const int is64 = g_idx_is64;
    const float4* __restrict__ wf4 = reinterpret_cast<const float4*>(weights);
    float4* __restrict__ of4 =
        reinterpret_cast<float4*>(out) + (size_t)b * (T_TABLES * D_DIM / 4);

    #pragma unroll 1
    for (int t = 0; t < T_TABLES; ++t) {
        // Each lane loads one of the 32 bag indices (coalesced, streaming).
        const size_t idx_off = ((size_t)t * B_BATCH + b) * L_BAG + lane;
        long long my_idx;
        if (is64) {
            my_idx = __ldcs(((const long long*)indices_raw) + idx_off);
        } else {
            my_idx = (long long)__ldcs(((const int*)indices_raw) + idx_off);
        }

        // Warp bitonic sort (ascending across lanes). Order within a bag is
        // irrelevant for SUM pooling; sorted order improves DRAM locality.
        #pragma unroll
        for (int k = 2; k <= 32; k <<= 1) {
            #pragma unroll
            for (int j = k >> 1; j > 0; j >>= 1) {
                const long long other = __shfl_xor_sync(0xffffffffu, my_idx, j);
                const bool upper_half = (lane & k) != 0;       // descending region
                const bool am_high   = (lane & j) != 0;        // high element of pair
                const long long mn = other < my_idx ? other : my_idx;
                const long long mx = other < my_idx ? my_idx : other;
                // ascending region: low lane keeps min; descending: inverted
                my_idx = (am_high != upper_half) ? mx : mn;
            }
        }

        const float4* __restrict__ wbase = wf4 + (size_t)t * E_ROWS * (D_DIM / 4);

        float4 acc = make_float4(0.f, 0.f, 0.f, 0.f);
        #pragma unroll
        for (int l = 0; l < L_BAG; ++l) {
            const long long row = __shfl_sync(0xffffffffu, my_idx, l);
            const float4 v = __ldg(wbase + (size_t)row * (D_DIM / 4) + lane);
            acc.x += v.x; acc.y += v.y; acc.z += v.z; acc.w += v.w;
        }

        // Streaming store: output is never re-read; don't pollute L2.
        __stcs(of4 + t * (D_DIM / 4) + lane, acc);
    }
}

extern "C" void kernel_launch(void* const* d_in, const int* in_sizes, int n_in,
                              void* d_out, int out_size)
{
    // Identify inputs by element count (robust to metadata ordering):
    // indices: T*B*L = 1,048,576 ; weights: T*E*D = 512,000,000
    const void*  indices = d_in[0];
    const float* weights = (const float*)d_in[1];
    if (n_in >= 2) {
        long long s0 = in_sizes[0], s1 = in_sizes[1];
        if (s0 > s1) {
            weights = (const float*)d_in[0];
            indices = d_in[1];
        }
    }
    float* out = (float*)d_out;

    probe_idx_dtype<<<1, 32>>>((const long long*)indices);

    const int blocks  = B_BATCH / 8;   // 1024 blocks x 8 warps = 8192 warps, 1 wave
    const int threads = 256;
    embbag_kernel<<<blocks, threads>>>(indices, weights, out);
}

// round 5
// speedup vs baseline: 1.0213x; 1.0213x over previous
#include <cuda_runtime.h>
#include <cstdint>

// T=4 tables, E=1,000,000 rows/table, D=128 dims, B=8192 bags, L=32 bag length
// indices: [T, B, L] (int32 OR int64 — detected inline per block)
// weights: fp32 [T, E, D]; output: fp32 [B, T*D]
// out[b, t*D + d] = sum_l weights[t, indices[t,b,l], d]

#define T_TABLES 4
#define E_ROWS   1000000
#define D_DIM    128
#define B_BATCH  8192
#define L_BAG    32

// One warp per bag b, looping over the 4 tables in phase order. 8192 warps =
// 1024 blocks x 8 warps = exactly one wave on 148 SMs; all resident warps
// stream the SAME table's ~131MB footprint concurrently so L2 captures the
// ~12% repeated rows. __syncthreads() between table phases keeps blocks
// phase-aligned (measured ~1us better than t-major, R3 vs R2).
//
// Index dtype is detected inline: warp 0 reads idx[0..31] as an int64 view.
// True int64 data (row ids < 1M) passes the range check on all lanes; int32
// data viewed as int64 has random row-ids in the hi-words, so P(all 32 pass)
// ~= (1e-6)^32 ~ 0. Costs one 256B L2-resident load + one barrier per block.
__global__ __launch_bounds__(256) void embbag_kernel(
    const void*  __restrict__ indices_raw,   // [T*B*L] int32 or int64
    const float* __restrict__ weights,       // [T*E*D]
    float*       __restrict__ out)           // [B*T*D]
{
    __shared__ int s_is64;

    const int lane = threadIdx.x & 31;
    const int b    = blockIdx.x * 8 + (threadIdx.x >> 5);   // 0..8191, exact

    if (threadIdx.x < 32) {
        const long long v = ((const long long*)indices_raw)[threadIdx.x];
        const unsigned bad = __ballot_sync(0xffffffffu, v < 0 || v >= E_ROWS);
        if (threadIdx.x == 0) s_is64 = (bad == 0u) ? 1 : 0;
    }
    __syncthreads();
    const int is64 = s_is64;

    const float4* __restrict__ wf4 = reinterpret_cast<const float4*>(weights);
    float4* __restrict__ of4 =
        reinterpret_cast<float4*>(out) + (size_t)b * (T_TABLES * D_DIM / 4);

    #pragma unroll 1
    for (int t = 0; t < T_TABLES; ++t) {
        // Each lane loads one of the 32 bag indices (coalesced, streaming).
        const size_t idx_off = ((size_t)t * B_BATCH + b) * L_BAG + lane;
        long long my_idx;
        if (is64) {
            my_idx = __ldcs(((const long long*)indices_raw) + idx_off);
        } else {
            my_idx = (long long)__ldcs(((const int*)indices_raw) + idx_off);
        }

        const float4* __restrict__ wbase = wf4 + (size_t)t * E_ROWS * (D_DIM / 4);

        float4 acc = make_float4(0.f, 0.f, 0.f, 0.f);
        #pragma unroll
        for (int l = 0; l < L_BAG; ++l) {
            const long long row = __shfl_sync(0xffffffffu, my_idx, l);
            const float4 v = __ldg(wbase + (size_t)row * (D_DIM / 4) + lane);
            acc.x += v.x; acc.y += v.y; acc.z += v.z; acc.w += v.w;
        }

        // Streaming store: output is never re-read; don't pollute L2.
        __stcs(of4 + t * (D_DIM / 4) + lane, acc);

        // Keep the block phase-aligned on the same table for L2 locality.
        __syncthreads();
    }
}

extern "C" void kernel_launch(void* const* d_in, const int* in_sizes, int n_in,
                              void* d_out, int out_size)
{
    // Identify inputs by element count (robust to metadata ordering):
    // indices: T*B*L = 1,048,576 ; weights: T*E*D = 512,000,000
    const void*  indices = d_in[0];
    const float* weights = (const float*)d_in[1];
    if (n_in >= 2) {
        long long s0 = in_sizes[0], s1 = in_sizes[1];
        if (s0 > s1) {
            weights = (const float*)d_in[0];
            indices = d_in[1];
        }
    }
    float* out = (float*)d_out;

    const int blocks  = B_BATCH / 8;   // 1024 blocks x 8 warps = 8192 warps, 1 wave
    const int threads = 256;
    embbag_kernel<<<blocks, threads>>>(indices, weights, out);
}